// round 5
// baseline (speedup 1.0000x reference)
#include <cuda_runtime.h>
#include <math_constants.h>

#define BB 2
#define NNq 2048
#define CCc 1024
#define HHh 16
#define DDd 64
#define MMm (BB*NNq)   // 4096

// Packed fp32x2 helpers (Blackwell sm_103a; PTX ISA 8.6+). Each lane is an
// exact IEEE fp32 op — numerics identical to scalar FFMA.
#define PACK_F32X2(out, lo, hi) \
    asm("mov.b64 %0, {%1, %2};" : "=l"(out) : "r"(lo), "r"(hi))
#define UNPACK_F32X2(lo, hi, in) \
    asm("mov.b64 {%0, %1}, %2;" : "=r"(lo), "=r"(hi) : "l"(in))
#define FMA_F32X2(d, a, b, c) \
    asm("fma.rn.f32x2 %0, %1, %2, %3;" : "=l"(d) : "l"(a), "l"(b), "l"(c))
#define MUL_F32X2(d, a, b) \
    asm("mul.rn.f32x2 %0, %1, %2;" : "=l"(d) : "l"(a), "l"(b))

__device__ __forceinline__ unsigned long long pack2(float lo, float hi) {
    unsigned long long r;
    PACK_F32X2(r, __float_as_uint(lo), __float_as_uint(hi));
    return r;
}
__device__ __forceinline__ void unpack2(unsigned long long p, float& lo, float& hi) {
    unsigned int a, b;
    UNPACK_F32X2(a, b, p);
    lo = __uint_as_float(a);
    hi = __uint_as_float(b);
}

// Scratch (allocation-free rule: static device globals)
__device__ float g_q[BB*NNq*CCc];
__device__ float g_k[BB*NNq*CCc];
__device__ float g_v[BB*NNq*CCc];
__device__ float g_ao[BB*NNq*CCc];

// ---------------------------------------------------------------------------
// GEMM: Y[M,N] = X[M,K] * W[N,K]^T + bias[N]
// 64x64 block tile, K-step 16, 256 threads, 4x4 per thread.
// Inner product issued as packed f32x2 FMAs (8 FMA2/iter instead of 16 FFMA).
// ---------------------------------------------------------------------------
__global__ __launch_bounds__(256) void gemm_bias_kernel(
    const float* __restrict__ X, const float* __restrict__ W,
    const float* __restrict__ bias, float* __restrict__ Y,
    int M, int Nn, int K)
{
    __shared__ float Xs[16][68];
    __shared__ float Ws[16][68];
    const int tid = threadIdx.x;
    const int tx = tid & 15, ty = tid >> 4;
    const int bm = blockIdx.y * 64, bn = blockIdx.x * 64;

    unsigned long long acc2[4][2];
#pragma unroll
    for (int i = 0; i < 4; i++) {
        acc2[i][0] = 0ull;   // (0.f, 0.f)
        acc2[i][1] = 0ull;
    }

    for (int k0 = 0; k0 < K; k0 += 16) {
#pragma unroll
        for (int i = 0; i < 4; i++) {
            int idx = tid + i * 256;
            int r = idx >> 4, kk = idx & 15;
            Xs[kk][r] = X[(size_t)(bm + r) * K + k0 + kk];
            Ws[kk][r] = W[(size_t)(bn + r) * K + k0 + kk];
        }
        __syncthreads();
#pragma unroll
        for (int kk = 0; kk < 16; kk++) {
            float4 xa = *(const float4*)&Xs[kk][ty * 4];
            float4 wb = *(const float4*)&Ws[kk][tx * 4];
            unsigned long long wb01 = pack2(wb.x, wb.y);
            unsigned long long wb23 = pack2(wb.z, wb.w);
            float xr[4] = {xa.x, xa.y, xa.z, xa.w};
#pragma unroll
            for (int i = 0; i < 4; i++) {
                unsigned long long xd = pack2(xr[i], xr[i]);
                FMA_F32X2(acc2[i][0], xd, wb01, acc2[i][0]);
                FMA_F32X2(acc2[i][1], xd, wb23, acc2[i][1]);
            }
        }
        __syncthreads();
    }

    float4 b4 = *(const float4*)&bias[bn + tx * 4];
#pragma unroll
    for (int i = 0; i < 4; i++) {
        float a0, a1, a2, a3;
        unpack2(acc2[i][0], a0, a1);
        unpack2(acc2[i][1], a2, a3);
        float4 o;
        o.x = a0 + b4.x;
        o.y = a1 + b4.y;
        o.z = a2 + b4.z;
        o.w = a3 + b4.w;
        *(float4*)&Y[(size_t)(bm + ty * 4 + i) * Nn + bn + tx * 4] = o;
    }
}

// ---------------------------------------------------------------------------
// Flash-style attention with additive bias.
// Grid: (N/64, H, B), 256 threads. Each CTA: 64 q-rows of one (b,h).
// QK and PV inner loops use packed f32x2 FMAs; softmax/bias stay scalar.
// ---------------------------------------------------------------------------
__global__ __launch_bounds__(256) void attn_kernel(
    const float* __restrict__ q, const float* __restrict__ k,
    const float* __restrict__ v, const float* __restrict__ bias,
    float* __restrict__ out)
{
    extern __shared__ float sm[];
    float* Qt = sm;                  // [64 d][68] : Qt[d][r]
    float* Kt = sm + 64 * 68;        // [64 d][68] : Kt[d][c]
    float* Vs = sm + 2 * 64 * 68;    // [64 c][68] : Vs[c][d]
    float* Pt = sm + 3 * 64 * 68;    // [64 c][68] : Pt[c][r]

    const int tid = threadIdx.x;
    const int tx = tid & 15, ty = tid >> 4;
    const int q0 = blockIdx.x * 64;
    const int h = blockIdx.y, b = blockIdx.z;
    const float scale = 0.125f;  // 1/sqrt(64)

    const size_t qbase = ((size_t)b * NNq + q0) * CCc + (size_t)h * DDd;

    // Load Q tile transposed: Qt[d][r]
#pragma unroll
    for (int i = 0; i < 16; i++) {
        int idx = tid + i * 256;       // 0..4095
        int r = idx >> 6, d = idx & 63;
        Qt[d * 68 + r] = q[qbase + (size_t)r * CCc + d];
    }

    float m_i[4], l_i[4];
    unsigned long long o2[4][2];     // packed O accumulators (pairs over dim j)
#pragma unroll
    for (int i = 0; i < 4; i++) {
        m_i[i] = -CUDART_INF_F;
        l_i[i] = 0.f;
        o2[i][0] = 0ull;
        o2[i][1] = 0ull;
    }

    for (int kt = 0; kt < NNq / 64; kt++) {
        const int k0 = kt * 64;
        __syncthreads();   // prior iter done reading Kt/Vs/Pt
        const size_t kbase = ((size_t)b * NNq + k0) * CCc + (size_t)h * DDd;
#pragma unroll
        for (int i = 0; i < 16; i++) {
            int idx = tid + i * 256;
            int c = idx >> 6, d = idx & 63;
            float kvv = k[kbase + (size_t)c * CCc + d];
            float vvv = v[kbase + (size_t)c * CCc + d];
            Kt[d * 68 + c] = kvv;
            Vs[c * 68 + d] = vvv;
        }
        __syncthreads();

        // S = Q K^T  (packed: 8 FMA2 per d instead of 16 FFMA)
        unsigned long long s2[4][2];
#pragma unroll
        for (int i = 0; i < 4; i++) { s2[i][0] = 0ull; s2[i][1] = 0ull; }

#pragma unroll 16
        for (int d = 0; d < 64; d++) {
            float4 qv = *(const float4*)&Qt[d * 68 + ty * 4];  // broadcast
            float4 kv = *(const float4*)&Kt[d * 68 + tx * 4];  // stride-1
            unsigned long long k01 = pack2(kv.x, kv.y);
            unsigned long long k23 = pack2(kv.z, kv.w);
            float qa[4] = {qv.x, qv.y, qv.z, qv.w};
#pragma unroll
            for (int i = 0; i < 4; i++) {
                unsigned long long qd = pack2(qa[i], qa[i]);
                FMA_F32X2(s2[i][0], qd, k01, s2[i][0]);
                FMA_F32X2(s2[i][1], qd, k23, s2[i][1]);
            }
        }

        // unpack S, scale + bias (bias shape (1,H,N,N), broadcast over batch)
        float s[4][4];
        const float* bptr = bias + ((size_t)h * NNq + q0 + ty * 4) * NNq + k0 + tx * 4;
#pragma unroll
        for (int i = 0; i < 4; i++) {
            unpack2(s2[i][0], s[i][0], s[i][1]);
            unpack2(s2[i][1], s[i][2], s[i][3]);
            float4 bv = *(const float4*)(bptr + (size_t)i * NNq);
            s[i][0] = s[i][0] * scale + bv.x;
            s[i][1] = s[i][1] * scale + bv.y;
            s[i][2] = s[i][2] * scale + bv.z;
            s[i][3] = s[i][3] * scale + bv.w;
        }

        // online softmax (row stats replicated across the 16 tx lanes)
#pragma unroll
        for (int i = 0; i < 4; i++) {
            float mx = fmaxf(fmaxf(s[i][0], s[i][1]), fmaxf(s[i][2], s[i][3]));
            mx = fmaxf(mx, __shfl_xor_sync(0xffffffffu, mx, 1));
            mx = fmaxf(mx, __shfl_xor_sync(0xffffffffu, mx, 2));
            mx = fmaxf(mx, __shfl_xor_sync(0xffffffffu, mx, 4));
            mx = fmaxf(mx, __shfl_xor_sync(0xffffffffu, mx, 8));
            float mn = fmaxf(m_i[i], mx);
            float alpha = __expf(m_i[i] - mn);
            m_i[i] = mn;
            float rs = 0.f;
#pragma unroll
            for (int j = 0; j < 4; j++) {
                s[i][j] = __expf(s[i][j] - mn);
                rs += s[i][j];
            }
            rs += __shfl_xor_sync(0xffffffffu, rs, 1);
            rs += __shfl_xor_sync(0xffffffffu, rs, 2);
            rs += __shfl_xor_sync(0xffffffffu, rs, 4);
            rs += __shfl_xor_sync(0xffffffffu, rs, 8);
            l_i[i] = l_i[i] * alpha + rs;
            // rescale packed O accumulators
            unsigned long long ad = pack2(alpha, alpha);
            MUL_F32X2(o2[i][0], o2[i][0], ad);
            MUL_F32X2(o2[i][1], o2[i][1], ad);
        }

        // write P transposed: Pt[c][r]
#pragma unroll
        for (int j = 0; j < 4; j++)
#pragma unroll
            for (int i = 0; i < 4; i++)
                Pt[(tx * 4 + j) * 68 + ty * 4 + i] = s[i][j];
        __syncthreads();

        // O += P V  (packed: 8 FMA2 per c instead of 16 FFMA)
#pragma unroll 8
        for (int c = 0; c < 64; c++) {
            float4 pv = *(const float4*)&Pt[c * 68 + ty * 4];  // broadcast
            float4 vv = *(const float4*)&Vs[c * 68 + tx * 4];  // stride-1
            unsigned long long v01 = pack2(vv.x, vv.y);
            unsigned long long v23 = pack2(vv.z, vv.w);
            float pa[4] = {pv.x, pv.y, pv.z, pv.w};
#pragma unroll
            for (int i = 0; i < 4; i++) {
                unsigned long long pd = pack2(pa[i], pa[i]);
                FMA_F32X2(o2[i][0], pd, v01, o2[i][0]);
                FMA_F32X2(o2[i][1], pd, v23, o2[i][1]);
            }
        }
    }

    // normalize + write out (layout (B,N,H,D) == (B,N,C))
#pragma unroll
    for (int i = 0; i < 4; i++) {
        float inv = 1.f / l_i[i];
        float a0, a1, a2, a3;
        unpack2(o2[i][0], a0, a1);
        unpack2(o2[i][1], a2, a3);
        float4 o;
        o.x = a0 * inv;
        o.y = a1 * inv;
        o.z = a2 * inv;
        o.w = a3 * inv;
        *(float4*)&out[qbase + (size_t)(ty * 4 + i) * CCc + tx * 4] = o;
    }
}

// ---------------------------------------------------------------------------

extern "C" void kernel_launch(void* const* d_in, const int* in_sizes, int n_in,
                              void* d_out, int out_size) {
    const float* x    = (const float*)d_in[0];
    const float* ctx  = (const float*)d_in[1];
    const float* bias = (const float*)d_in[2];
    const float* Wq   = (const float*)d_in[3];
    const float* bq   = (const float*)d_in[4];
    const float* Wk   = (const float*)d_in[5];
    const float* bk   = (const float*)d_in[6];
    const float* Wv   = (const float*)d_in[7];
    const float* bv   = (const float*)d_in[8];
    const float* Wo   = (const float*)d_in[9];
    const float* bo   = (const float*)d_in[10];
    float* out = (float*)d_out;

    float *qbuf, *kbuf, *vbuf, *aobuf;
    cudaGetSymbolAddress((void**)&qbuf,  g_q);
    cudaGetSymbolAddress((void**)&kbuf,  g_k);
    cudaGetSymbolAddress((void**)&vbuf,  g_v);
    cudaGetSymbolAddress((void**)&aobuf, g_ao);

    dim3 gg(CCc / 64, MMm / 64);
    gemm_bias_kernel<<<gg, 256>>>(x,   Wq, bq, qbuf, MMm, CCc, CCc);
    gemm_bias_kernel<<<gg, 256>>>(ctx, Wk, bk, kbuf, MMm, CCc, CCc);
    gemm_bias_kernel<<<gg, 256>>>(ctx, Wv, bv, vbuf, MMm, CCc, CCc);

    const size_t attn_smem = 4 * 64 * 68 * sizeof(float);  // 69632 B
    cudaFuncSetAttribute(attn_kernel,
                         cudaFuncAttributeMaxDynamicSharedMemorySize,
                         (int)attn_smem);
    attn_kernel<<<dim3(NNq / 64, HHh, BB), 256, attn_smem>>>(
        qbuf, kbuf, vbuf, bias, aobuf);

    gemm_bias_kernel<<<gg, 256>>>(aobuf, Wo, bo, out, MMm, CCc, CCc);
}

// round 9
// speedup vs baseline: 1.4391x; 1.4391x over previous
#include <cuda_runtime.h>
#include <cuda_bf16.h>
#include <math_constants.h>
#include <cstdint>

#define BB 2
#define NNq 2048
#define CCc 1024
#define HHh 16
#define DDd 64
#define MMm (BB*NNq)   // 4096

// ===========================================================================
// Warp-level MMA helpers (portable PTX, no sm_103a-only features)
// ===========================================================================
__device__ __forceinline__ uint32_t smem_to_u32(const void* p) {
    uint32_t a;
    asm("{ .reg .u64 t; cvta.to.shared.u64 t, %1; cvt.u32.u64 %0, t; }"
        : "=r"(a) : "l"(p));
    return a;
}

__device__ __forceinline__ void ldsm_x4(uint32_t& r0, uint32_t& r1,
                                        uint32_t& r2, uint32_t& r3,
                                        uint32_t addr) {
    asm volatile("ldmatrix.sync.aligned.m8n8.x4.shared.b16 {%0,%1,%2,%3}, [%4];"
        : "=r"(r0), "=r"(r1), "=r"(r2), "=r"(r3) : "r"(addr));
}

__device__ __forceinline__ void mma_bf16(float* c, const uint32_t* a,
                                         const uint32_t* b) {
    asm volatile(
        "mma.sync.aligned.m16n8k16.row.col.f32.bf16.bf16.f32 "
        "{%0,%1,%2,%3}, {%4,%5,%6,%7}, {%8,%9}, {%0,%1,%2,%3};"
        : "+f"(c[0]), "+f"(c[1]), "+f"(c[2]), "+f"(c[3])
        : "r"(a[0]), "r"(a[1]), "r"(a[2]), "r"(a[3]), "r"(b[0]), "r"(b[1]));
}

// Packed fp32x2 helpers for the SIMT attention kernel
#define PACK_F32X2(out, lo, hi) \
    asm("mov.b64 %0, {%1, %2};" : "=l"(out) : "r"(lo), "r"(hi))
#define UNPACK_F32X2(lo, hi, in) \
    asm("mov.b64 {%0, %1}, %2;" : "=r"(lo), "=r"(hi) : "l"(in))
#define FMA_F32X2(d, a, b, c) \
    asm("fma.rn.f32x2 %0, %1, %2, %3;" : "=l"(d) : "l"(a), "l"(b), "l"(c))
#define MUL_F32X2(d, a, b) \
    asm("mul.rn.f32x2 %0, %1, %2;" : "=l"(d) : "l"(a), "l"(b))

__device__ __forceinline__ unsigned long long pack2(float lo, float hi) {
    unsigned long long r;
    PACK_F32X2(r, __float_as_uint(lo), __float_as_uint(hi));
    return r;
}
__device__ __forceinline__ void unpack2(unsigned long long p, float& lo, float& hi) {
    unsigned int a, b;
    UNPACK_F32X2(a, b, p);
    lo = __uint_as_float(a);
    hi = __uint_as_float(b);
}

// Split a float4 into packed-bf16 hi and lo residual halves
__device__ __forceinline__ void split_f4(float4 a, uint2& hi, uint2& lo) {
    __nv_bfloat16 h0 = __float2bfloat16(a.x);
    __nv_bfloat16 h1 = __float2bfloat16(a.y);
    __nv_bfloat16 h2 = __float2bfloat16(a.z);
    __nv_bfloat16 h3 = __float2bfloat16(a.w);
    __nv_bfloat16 l0 = __float2bfloat16(a.x - __bfloat162float(h0));
    __nv_bfloat16 l1 = __float2bfloat16(a.y - __bfloat162float(h1));
    __nv_bfloat16 l2 = __float2bfloat16(a.z - __bfloat162float(h2));
    __nv_bfloat16 l3 = __float2bfloat16(a.w - __bfloat162float(h3));
    hi.x = ((uint32_t)__bfloat16_as_ushort(h1) << 16) | __bfloat16_as_ushort(h0);
    hi.y = ((uint32_t)__bfloat16_as_ushort(h3) << 16) | __bfloat16_as_ushort(h2);
    lo.x = ((uint32_t)__bfloat16_as_ushort(l1) << 16) | __bfloat16_as_ushort(l0);
    lo.y = ((uint32_t)__bfloat16_as_ushort(l3) << 16) | __bfloat16_as_ushort(l2);
}

// Scratch (allocation-free rule: static device globals)
__device__ float g_q[BB*NNq*CCc];
__device__ float g_k[BB*NNq*CCc];
__device__ float g_v[BB*NNq*CCc];
__device__ float g_ao[BB*NNq*CCc];

// ===========================================================================
// HMMA GEMM: Y[M,N] = X[M,K] * W[N,K]^T + bias[N]
// CTA 128x128, BK=32. bf16 hi/lo split, 3-pass mma.sync (fp32 accum).
// 8 warps: warp_m = wid&1 (2 x 64 rows), warp_n = wid>>1 (4 x 32 cols).
// smem row stride 40 bf16 (80B): conflict-free for ldmatrix (proof: 8 rows at
// 20-word stride hit banks {0,20,8,28,16,4,24,12}, disjoint 16B spans).
// ===========================================================================
#define GK 1024

__global__ __launch_bounds__(256) void gemm_mma_kernel(
    const float* __restrict__ X, const float* __restrict__ W,
    const float* __restrict__ bias, float* __restrict__ Y, int Nn)
{
    __shared__ __nv_bfloat16 Ah[128][40];
    __shared__ __nv_bfloat16 Al[128][40];
    __shared__ __nv_bfloat16 Bh[128][40];
    __shared__ __nv_bfloat16 Bl[128][40];

    const int tid = threadIdx.x;
    const int wid = tid >> 5, lid = tid & 31;
    const int warp_m = wid & 1, warp_n = wid >> 1;
    const int bm = blockIdx.y * 128, bn = blockIdx.x * 128;

    float acc[4][4][4];
#pragma unroll
    for (int mt = 0; mt < 4; mt++)
#pragma unroll
        for (int nt = 0; nt < 4; nt++)
#pragma unroll
            for (int r = 0; r < 4; r++) acc[mt][nt][r] = 0.f;

    // precomputed ldmatrix lane addressing pieces
    const int a_row = (lid & 15);
    const int a_kof = ((lid >> 4) & 1) * 8;
    const int b_row = ((lid >> 4) & 1) * 8 + (lid & 7);
    const int b_kof = ((lid >> 3) & 1) * 8;

    for (int kt = 0; kt < GK; kt += 32) {
#pragma unroll
        for (int i = 0; i < 4; i++) {
            int lin = tid + i * 256;        // 0..1023
            int row = lin >> 3;             // 0..127
            int c4  = lin & 7;              // 0..7 float4 within 32 floats
            uint2 hi, lo;
            float4 a = *(const float4*)(X + (size_t)(bm + row) * GK + kt + c4 * 4);
            split_f4(a, hi, lo);
            *(uint2*)&Ah[row][c4 * 4] = hi;
            *(uint2*)&Al[row][c4 * 4] = lo;
            float4 b = *(const float4*)(W + (size_t)(bn + row) * GK + kt + c4 * 4);
            split_f4(b, hi, lo);
            *(uint2*)&Bh[row][c4 * 4] = hi;
            *(uint2*)&Bl[row][c4 * 4] = lo;
        }
        __syncthreads();

#pragma unroll
        for (int sub = 0; sub < 2; sub++) {
            const int k16 = sub * 16;
            // B fragments: one x4 covers two n8 tiles (hi and lo variants)
            uint32_t bh[4][2], bl[4][2];
#pragma unroll
            for (int ntp = 0; ntp < 2; ntp++) {
                int n0 = warp_n * 32 + ntp * 16;
                uint32_t ah_ = smem_to_u32(&Bh[n0 + b_row][k16 + b_kof]);
                ldsm_x4(bh[ntp*2][0], bh[ntp*2][1], bh[ntp*2+1][0], bh[ntp*2+1][1], ah_);
                uint32_t al_ = smem_to_u32(&Bl[n0 + b_row][k16 + b_kof]);
                ldsm_x4(bl[ntp*2][0], bl[ntp*2][1], bl[ntp*2+1][0], bl[ntp*2+1][1], al_);
            }
#pragma unroll
            for (int mt = 0; mt < 4; mt++) {
                int m0 = warp_m * 64 + mt * 16;
                uint32_t ah[4], al[4];
                ldsm_x4(ah[0], ah[1], ah[2], ah[3],
                        smem_to_u32(&Ah[m0 + a_row][k16 + a_kof]));
                ldsm_x4(al[0], al[1], al[2], al[3],
                        smem_to_u32(&Al[m0 + a_row][k16 + a_kof]));
#pragma unroll
                for (int nt = 0; nt < 4; nt++) {
                    mma_bf16(acc[mt][nt], ah, bh[nt]);
                    mma_bf16(acc[mt][nt], ah, bl[nt]);
                    mma_bf16(acc[mt][nt], al, bh[nt]);
                }
            }
        }
        __syncthreads();
    }

    // Epilogue: c0,c1 -> (row gi, cols 2*ti..+1); c2,c3 -> row gi+8
    const int gi = lid >> 2;
    const int ti = lid & 3;
#pragma unroll
    for (int mt = 0; mt < 4; mt++) {
        int r0 = bm + warp_m * 64 + mt * 16 + gi;
#pragma unroll
        for (int nt = 0; nt < 4; nt++) {
            int c = bn + warp_n * 32 + nt * 8 + ti * 2;
            float b0 = bias[c], b1 = bias[c + 1];
            float2 o0 = make_float2(acc[mt][nt][0] + b0, acc[mt][nt][1] + b1);
            *(float2*)&Y[(size_t)r0 * Nn + c] = o0;
            float2 o1 = make_float2(acc[mt][nt][2] + b0, acc[mt][nt][3] + b1);
            *(float2*)&Y[(size_t)(r0 + 8) * Nn + c] = o1;
        }
    }
}

// ===========================================================================
// Flash-style attention with additive bias (unchanged from measured 967us).
// ===========================================================================
__global__ __launch_bounds__(256) void attn_kernel(
    const float* __restrict__ q, const float* __restrict__ k,
    const float* __restrict__ v, const float* __restrict__ bias,
    float* __restrict__ out)
{
    extern __shared__ float sm[];
    float* Qt = sm;                  // [64 d][68] : Qt[d][r]
    float* Kt = sm + 64 * 68;        // [64 d][68] : Kt[d][c]
    float* Vs = sm + 2 * 64 * 68;    // [64 c][68] : Vs[c][d]
    float* Pt = sm + 3 * 64 * 68;    // [64 c][68] : Pt[c][r]

    const int tid = threadIdx.x;
    const int tx = tid & 15, ty = tid >> 4;
    const int q0 = blockIdx.x * 64;
    const int h = blockIdx.y, b = blockIdx.z;
    const float scale = 0.125f;  // 1/sqrt(64)

    const size_t qbase = ((size_t)b * NNq + q0) * CCc + (size_t)h * DDd;

#pragma unroll
    for (int i = 0; i < 16; i++) {
        int idx = tid + i * 256;
        int r = idx >> 6, d = idx & 63;
        Qt[d * 68 + r] = q[qbase + (size_t)r * CCc + d];
    }

    float m_i[4], l_i[4];
    unsigned long long o2[4][2];
#pragma unroll
    for (int i = 0; i < 4; i++) {
        m_i[i] = -CUDART_INF_F;
        l_i[i] = 0.f;
        o2[i][0] = 0ull;
        o2[i][1] = 0ull;
    }

    for (int kt = 0; kt < NNq / 64; kt++) {
        const int k0 = kt * 64;
        __syncthreads();
        const size_t kbase = ((size_t)b * NNq + k0) * CCc + (size_t)h * DDd;
#pragma unroll
        for (int i = 0; i < 16; i++) {
            int idx = tid + i * 256;
            int c = idx >> 6, d = idx & 63;
            float kvv = k[kbase + (size_t)c * CCc + d];
            float vvv = v[kbase + (size_t)c * CCc + d];
            Kt[d * 68 + c] = kvv;
            Vs[c * 68 + d] = vvv;
        }
        __syncthreads();

        unsigned long long s2[4][2];
#pragma unroll
        for (int i = 0; i < 4; i++) { s2[i][0] = 0ull; s2[i][1] = 0ull; }

#pragma unroll 16
        for (int d = 0; d < 64; d++) {
            float4 qv = *(const float4*)&Qt[d * 68 + ty * 4];
            float4 kv = *(const float4*)&Kt[d * 68 + tx * 4];
            unsigned long long k01 = pack2(kv.x, kv.y);
            unsigned long long k23 = pack2(kv.z, kv.w);
            float qa[4] = {qv.x, qv.y, qv.z, qv.w};
#pragma unroll
            for (int i = 0; i < 4; i++) {
                unsigned long long qd = pack2(qa[i], qa[i]);
                FMA_F32X2(s2[i][0], qd, k01, s2[i][0]);
                FMA_F32X2(s2[i][1], qd, k23, s2[i][1]);
            }
        }

        float s[4][4];
        const float* bptr = bias + ((size_t)h * NNq + q0 + ty * 4) * NNq + k0 + tx * 4;
#pragma unroll
        for (int i = 0; i < 4; i++) {
            unpack2(s2[i][0], s[i][0], s[i][1]);
            unpack2(s2[i][1], s[i][2], s[i][3]);
            float4 bv = *(const float4*)(bptr + (size_t)i * NNq);
            s[i][0] = s[i][0] * scale + bv.x;
            s[i][1] = s[i][1] * scale + bv.y;
            s[i][2] = s[i][2] * scale + bv.z;
            s[i][3] = s[i][3] * scale + bv.w;
        }

#pragma unroll
        for (int i = 0; i < 4; i++) {
            float mx = fmaxf(fmaxf(s[i][0], s[i][1]), fmaxf(s[i][2], s[i][3]));
            mx = fmaxf(mx, __shfl_xor_sync(0xffffffffu, mx, 1));
            mx = fmaxf(mx, __shfl_xor_sync(0xffffffffu, mx, 2));
            mx = fmaxf(mx, __shfl_xor_sync(0xffffffffu, mx, 4));
            mx = fmaxf(mx, __shfl_xor_sync(0xffffffffu, mx, 8));
            float mn = fmaxf(m_i[i], mx);
            float alpha = __expf(m_i[i] - mn);
            m_i[i] = mn;
            float rs = 0.f;
#pragma unroll
            for (int j = 0; j < 4; j++) {
                s[i][j] = __expf(s[i][j] - mn);
                rs += s[i][j];
            }
            rs += __shfl_xor_sync(0xffffffffu, rs, 1);
            rs += __shfl_xor_sync(0xffffffffu, rs, 2);
            rs += __shfl_xor_sync(0xffffffffu, rs, 4);
            rs += __shfl_xor_sync(0xffffffffu, rs, 8);
            l_i[i] = l_i[i] * alpha + rs;
            unsigned long long ad = pack2(alpha, alpha);
            MUL_F32X2(o2[i][0], o2[i][0], ad);
            MUL_F32X2(o2[i][1], o2[i][1], ad);
        }

#pragma unroll
        for (int j = 0; j < 4; j++)
#pragma unroll
            for (int i = 0; i < 4; i++)
                Pt[(tx * 4 + j) * 68 + ty * 4 + i] = s[i][j];
        __syncthreads();

#pragma unroll 8
        for (int c = 0; c < 64; c++) {
            float4 pv = *(const float4*)&Pt[c * 68 + ty * 4];
            float4 vv = *(const float4*)&Vs[c * 68 + tx * 4];
            unsigned long long v01 = pack2(vv.x, vv.y);
            unsigned long long v23 = pack2(vv.z, vv.w);
            float pa[4] = {pv.x, pv.y, pv.z, pv.w};
#pragma unroll
            for (int i = 0; i < 4; i++) {
                unsigned long long pd = pack2(pa[i], pa[i]);
                FMA_F32X2(o2[i][0], pd, v01, o2[i][0]);
                FMA_F32X2(o2[i][1], pd, v23, o2[i][1]);
            }
        }
    }

#pragma unroll
    for (int i = 0; i < 4; i++) {
        float inv = 1.f / l_i[i];
        float a0, a1, a2, a3;
        unpack2(o2[i][0], a0, a1);
        unpack2(o2[i][1], a2, a3);
        float4 o;
        o.x = a0 * inv;
        o.y = a1 * inv;
        o.z = a2 * inv;
        o.w = a3 * inv;
        *(float4*)&out[qbase + (size_t)(ty * 4 + i) * CCc + tx * 4] = o;
    }
}

// ---------------------------------------------------------------------------

extern "C" void kernel_launch(void* const* d_in, const int* in_sizes, int n_in,
                              void* d_out, int out_size) {
    const float* x    = (const float*)d_in[0];
    const float* ctx  = (const float*)d_in[1];
    const float* bias = (const float*)d_in[2];
    const float* Wq   = (const float*)d_in[3];
    const float* bq   = (const float*)d_in[4];
    const float* Wk   = (const float*)d_in[5];
    const float* bk   = (const float*)d_in[6];
    const float* Wv   = (const float*)d_in[7];
    const float* bv   = (const float*)d_in[8];
    const float* Wo   = (const float*)d_in[9];
    const float* bo   = (const float*)d_in[10];
    float* out = (float*)d_out;

    float *qbuf, *kbuf, *vbuf, *aobuf;
    cudaGetSymbolAddress((void**)&qbuf,  g_q);
    cudaGetSymbolAddress((void**)&kbuf,  g_k);
    cudaGetSymbolAddress((void**)&vbuf,  g_v);
    cudaGetSymbolAddress((void**)&aobuf, g_ao);

    dim3 gg(CCc / 128, MMm / 128);   // (8, 32)
    gemm_mma_kernel<<<gg, 256>>>(x,   Wq, bq, qbuf, CCc);
    gemm_mma_kernel<<<gg, 256>>>(ctx, Wk, bk, kbuf, CCc);
    gemm_mma_kernel<<<gg, 256>>>(ctx, Wv, bv, vbuf, CCc);

    const size_t attn_smem = 4 * 64 * 68 * sizeof(float);  // 69632 B
    cudaFuncSetAttribute(attn_kernel,
                         cudaFuncAttributeMaxDynamicSharedMemorySize,
                         (int)attn_smem);
    attn_kernel<<<dim3(NNq / 64, HHh, BB), 256, attn_smem>>>(
        qbuf, kbuf, vbuf, bias, aobuf);

    gemm_mma_kernel<<<gg, 256>>>(aobuf, Wo, bo, out, CCc);
}